// round 14
// baseline (speedup 1.0000x reference)
#include <cuda_runtime.h>
#include <cuda_fp16.h>
#include <math.h>

#define N_NODES 20000
#define N_EDGES 50000
#define C 64
#define NREL 32
#define MAXTILES 424
#define ORDER_CAP (MAXTILES * 128)   // 54272

// ---------------- scratch (no allocations allowed) ----------------
struct __align__(16) GScratch {
    int cnt_src[N_NODES];
    int cnt_dst[N_NODES];
    int hist[NREL];
    int cursor[NREL];
};
__device__ GScratch G;
__device__ __align__(16) int4   g_rec[ORDER_CAP];       // src,dst,c0,c1 (pads: c=0)
__device__ __align__(16) __half g_wt[2 * NREL * 4096];  // fp16, n-major, swizzled
__device__ __align__(16) __half g_xh[N_NODES * C];      // fp16 copy of x
__device__ float g_inv[2][NREL];
__device__ int g_is64;

__device__ __forceinline__ int load_idx(const void* p, int i, int is64) {
    return is64 ? (int)((const long long*)p)[i] : ((const int*)p)[i];
}
__device__ __forceinline__ void mma_f16(float* d,
    unsigned a0, unsigned a1, unsigned a2, unsigned a3,
    unsigned b0, unsigned b1)
{
    asm volatile(
        "mma.sync.aligned.m16n8k16.row.col.f32.f16.f16.f32 "
        "{%0,%1,%2,%3},{%4,%5,%6,%7},{%8,%9},{%0,%1,%2,%3};"
        : "+f"(d[0]), "+f"(d[1]), "+f"(d[2]), "+f"(d[3])
        : "r"(a0), "r"(a1), "r"(a2), "r"(a3), "r"(b0), "r"(b1));
}
__device__ __forceinline__ void ldsm4(unsigned& r0, unsigned& r1,
                                      unsigned& r2, unsigned& r3, unsigned addr)
{
    asm volatile("ldmatrix.sync.aligned.m8n8.x4.shared.b16 {%0,%1,%2,%3}, [%4];"
                 : "=r"(r0), "=r"(r1), "=r"(r2), "=r"(r3) : "r"(addr));
}
__device__ __forceinline__ void red4(float* p, float a, float b, float c, float d) {
    asm volatile("red.global.add.v4.f32 [%0], {%1,%2,%3,%4};"
                 :: "l"(p), "f"(a), "f"(b), "f"(c), "f"(d) : "memory");
}
__device__ __forceinline__ void cpa16(unsigned dst, const void* src) {
    asm volatile("cp.async.ca.shared.global [%0], [%1], 16;"
                 :: "r"(dst), "l"(src) : "memory");
}
// fp16 tile layout: rows of 64 halves (128B), 8x16B groups, group XOR by row&7
__device__ __forceinline__ int swzh(int row, int k) {
    return row * 64 + (((k >> 3) ^ (row & 7)) << 3) + (k & 7);
}

#define N16_G ((int)(sizeof(GScratch) / 16))
#define ZERO_BLOCKS ((N16_G + 255) / 256)         // 40
#define XH_BLOCKS ((N_NODES * C) / 2048)          // 625
#define COUNT_BLOCKS ((N_EDGES + 255) / 256)      // 196

// ---------------- k0: zero counters + detect index width --------------------
__global__ __launch_bounds__(256) void k_zero(const void* __restrict__ ei)
{
    int b = blockIdx.x, tid = threadIdx.x;
    if (b < ZERO_BLOCKS) {
        int i = b * 256 + tid;
        if (i < N16_G) ((int4*)&G)[i] = make_int4(0, 0, 0, 0);
    } else {
        if (tid < 32) {
            int hi = ((const int*)ei)[2 * tid + 1];
            unsigned ok = __ballot_sync(0xFFFFFFFFu, hi == 0);
            if (tid == 0) g_is64 = (ok == 0xFFFFFFFFu) ? 1 : 0;
        }
    }
}

// ------- k1: [xh || norms] independent FIRST, count (PDL-dep) LAST ----------
__global__ __launch_bounds__(256) void k_cnx(
    const void* __restrict__ ei, const void* __restrict__ et,
    const float* __restrict__ wf, const float* __restrict__ wb,
    const float* __restrict__ x)
{
    int b = blockIdx.x, tid = threadIdx.x;
    if (b < XH_BLOCKS) {
        // x -> fp16 (independent of k0) — runs during k0 drain
        int i = b * 2048 + tid * 8;
        float4 v0 = *(const float4*)(x + i);
        float4 v1 = *(const float4*)(x + i + 4);
        __half h[8];
        h[0]=__float2half_rn(v0.x); h[1]=__float2half_rn(v0.y);
        h[2]=__float2half_rn(v0.z); h[3]=__float2half_rn(v0.w);
        h[4]=__float2half_rn(v1.x); h[5]=__float2half_rn(v1.y);
        h[6]=__float2half_rn(v1.z); h[7]=__float2half_rn(v1.w);
        *(int4*)(g_xh + i) = *(int4*)h;
    } else if (b < XH_BLOCKS + 64) {
        // per-relation norm + fp16 swizzled n-major tile (independent)
        __shared__ float red[256];
        int bb = b - XH_BLOCKS;
        int r = bb & 31, tab = bb >> 5;
        const float* w = (tab ? wb : wf) + (size_t)r * (C * C);
        __half* wt = g_wt + (size_t)bb * 4096;
        float s = 0.f;
        for (int j = tid; j < C * C; j += 256) {
            float v = w[j];
            s += v * v;
            int k = j >> 6, n = j & 63;          // gmem is [k][n]
            wt[swzh(n, k)] = __float2half_rn(v);
        }
        red[tid] = s; __syncthreads();
        for (int o = 128; o > 0; o >>= 1) {
            if (tid < o) red[tid] += red[tid + o];
            __syncthreads();
        }
        if (tid == 0) g_inv[tab][r] = 1.f / (sqrtf(red[0]) + 0.01f);
    } else {
        // count (needs zeroed G + g_is64 from k0)
        __shared__ int h[NREL];
        if (tid < NREL) h[tid] = 0;
        cudaGridDependencySynchronize();
        __syncthreads();
        int e = (b - XH_BLOCKS - 64) * 256 + tid;
        int is64 = g_is64;
        if (e < N_EDGES) {
            atomicAdd(&G.cnt_src[load_idx(ei, e, is64)], 1);
            atomicAdd(&G.cnt_dst[load_idx(ei, N_EDGES + e, is64)], 1);
            atomicAdd(&h[load_idx(et, e, is64)], 1);
        }
        __syncthreads();
        if (tid < NREL && h[tid]) atomicAdd(&G.hist[tid], h[tid]);
    }
}

// ====== fp16 tensor-core inner loop: 128x64 @ k=64, m16n8k16 ================
__device__ __forceinline__ void mma_main(
    unsigned sA, unsigned sB, int lane, int warp, float d[8][4])
{
    int arow = warp * 16 + (lane & 15);
    unsigned arowoff = (unsigned)arow * 128u;
    int ax = arow & 7;
    int aksel = lane >> 4;
    int nb = (lane & 7) + ((lane & 16) >> 1);
    int bksel = (lane >> 3) & 1;

    #pragma unroll
    for (int t = 0; t < 4; t++) {
        unsigned apg = (unsigned)((2 * t + aksel) ^ ax);
        unsigned a0, a1, a2, a3;
        ldsm4(a0, a1, a2, a3, sA + arowoff + apg * 16u);
        #pragma unroll
        for (int j = 0; j < 4; j++) {
            int n = 16 * j + nb;
            unsigned bpg = (unsigned)((2 * t + bksel) ^ (n & 7));
            unsigned b0, b1, b2, b3;
            ldsm4(b0, b1, b2, b3, sB + (unsigned)n * 128u + bpg * 16u);
            mma_f16(d[2 * j],     a0, a1, a2, a3, b0, b1);
            mma_f16(d[2 * j + 1], a0, a1, a2, a3, b2, b3);
        }
    }
}

// ------- k2: [linear (NO dep, from fp32 x) FIRST] + pad + scatter(dep) ------
#define SCAT_BLOCKS COUNT_BLOCKS
#define LIN_BLOCKS ((N_NODES + 127) / 128)
#define TC_SMEM_BYTES (16384 + 8192)             // A 16KB + B 8KB
#define SCAT_SMEM_BYTES TC_SMEM_BYTES

__global__ __launch_bounds__(256, 4) void k_scatlin(
    const void* __restrict__ ei, const void* __restrict__ et,
    const float* __restrict__ x,
    const float* __restrict__ lw, const float* __restrict__ lb,
    float* __restrict__ out)
{
    int tid = threadIdx.x;

    if (blockIdx.x < LIN_BLOCKS) {
        // ---- linear: out = x @ lw^T + b — fully independent of k0/k1 ----
        extern __shared__ char smc[];
        unsigned sbase = (unsigned)__cvta_generic_to_shared(smc);
        unsigned sA = sbase, sB = sbase + 16384u;
        __half* Ah = (__half*)smc;
        __half* Bh = (__half*)(smc + 16384);

        int node0 = blockIdx.x * 128;

        {   // A: convert fp32 x rows -> fp16 swizzled (LDG + cvt + STS)
            int m = tid & 127, h = tid >> 7;
            int node = node0 + m;
            if (node >= N_NODES) node = 0;
            const float4* xr = (const float4*)(x + (size_t)node * C + h * 32);
            #pragma unroll
            for (int q = 0; q < 4; q++) {
                float4 va = xr[2 * q], vb = xr[2 * q + 1];
                __half hh[8];
                hh[0]=__float2half_rn(va.x); hh[1]=__float2half_rn(va.y);
                hh[2]=__float2half_rn(va.z); hh[3]=__float2half_rn(va.w);
                hh[4]=__float2half_rn(vb.x); hh[5]=__float2half_rn(vb.y);
                hh[6]=__float2half_rn(vb.z); hh[7]=__float2half_rn(vb.w);
                int g = h * 4 + q;
                *(uint4*)&Ah[m * 64 + ((g ^ (m & 7)) << 3)] = *(uint4*)hh;
            }
        }
        {   // B = lw (n-major) -> fp16 swizzled
            const float4* w4 = (const float4*)lw;
            #pragma unroll
            for (int q = 0; q < 4; q++) {
                int i4 = tid + 256 * q;
                float4 v = w4[i4];
                int n = i4 >> 4, k0 = (i4 & 15) * 4;
                __half hh[4];
                hh[0]=__float2half_rn(v.x); hh[1]=__float2half_rn(v.y);
                hh[2]=__float2half_rn(v.z); hh[3]=__float2half_rn(v.w);
                *(uint2*)&Bh[swzh(n, k0)] = *(uint2*)hh;
            }
        }
        __syncthreads();

        int lane = tid & 31, w = tid >> 5;
        float d[8][4] = {};
        mma_main(sA, sB, lane, w, d);

        int gid = lane >> 2, tig = lane & 3;
        int r0 = w * 16 + gid, r1 = r0 + 8;
        #pragma unroll
        for (int j = 0; j < 8; j++) {
            int n = j * 8 + 2 * tig;
            float2 bias = *(const float2*)(lb + n);
            if (node0 + r0 < N_NODES)
                *(float2*)(out + (size_t)(node0 + r0) * C + n) =
                    make_float2(d[j][0] + bias.x, d[j][1] + bias.y);
            if (node0 + r1 < N_NODES)
                *(float2*)(out + (size_t)(node0 + r1) * C + n) =
                    make_float2(d[j][2] + bias.x, d[j][3] + bias.y);
        }
        return;
    }

    cudaGridDependencySynchronize();   // scatter/pad need k1 hist/cnt/inv

    if (blockIdx.x == LIN_BLOCKS) {
        // pad-fill zero records per relation
        __shared__ int pbase[NREL];
        __shared__ int pcnt[NREL];
        if (tid < 32) {
            int h = G.hist[tid];
            int nt = (h + 127) >> 7;
            int a = nt;
            #pragma unroll
            for (int o = 1; o < 32; o <<= 1) {
                int v = __shfl_up_sync(0xFFFFFFFFu, a, o);
                if (tid >= o) a += v;
            }
            pbase[tid] = (a - nt) * 128 + h;
            pcnt[tid]  = nt * 128 - h;
        }
        __syncthreads();
        for (int r = 0; r < NREL; r++) {
            int pn = pcnt[r];
            for (int i = tid; i < pn; i += 256)
                g_rec[pbase[r] + i] = make_int4(0, 0, 0, 0);
        }
        return;
    }

    {   // scatter: relation-sorted edge records
        __shared__ int obase[NREL];
        __shared__ int bcnt[NREL];
        __shared__ int gbase[NREL];
        if (tid < 32) {
            int nt = (G.hist[tid] + 127) >> 7;
            int a = nt;
            #pragma unroll
            for (int o = 1; o < 32; o <<= 1) {
                int v = __shfl_up_sync(0xFFFFFFFFu, a, o);
                if (tid >= o) a += v;
            }
            obase[tid] = (a - nt) * 128;
            bcnt[tid] = 0;
        }
        __syncthreads();
        int is64 = g_is64;
        int e = (blockIdx.x - LIN_BLOCKS - 1) * 256 + tid;
        int r = 0, my = 0, valid = (e < N_EDGES);
        if (valid) {
            r = load_idx(et, e, is64);
            my = atomicAdd(&bcnt[r], 1);
        }
        __syncthreads();
        if (tid < 32 && bcnt[tid]) gbase[tid] = atomicAdd(&G.cursor[tid], bcnt[tid]);
        __syncthreads();
        if (valid) {
            int pos = obase[r] + gbase[r] + my;
            int s  = load_idx(ei, e, is64);
            int dd = load_idx(ei, N_EDGES + e, is64);
            float c0 = g_inv[0][r] / (float)(G.cnt_src[s] + 1);
            float c1 = g_inv[1][r] / (float)(G.cnt_dst[dd] + 1);
            g_rec[pos] = make_int4(s, dd, __float_as_int(c0), __float_as_int(c1));
        }
    }
}

// ---------------- k3: conv (one-shot; fp16 mma; guarded red4) ---------------
#define CONV_SMEM_BYTES (TC_SMEM_BYTES + (128 * 2 + 33) * 4)
#define CONV_GRID (2 * (MAXTILES - 2))            // 844

__global__ __launch_bounds__(256, 4) void k_conv(float* __restrict__ out)
{
    extern __shared__ char smc[];
    int*   Ds  = (int*)(smc + 24576);
    float* Cs  = (float*)(Ds + 128);
    int*   Tst = (int*)(Cs + 128);
    unsigned sbase = (unsigned)__cvta_generic_to_shared(smc);
    unsigned sA = sbase, sB = sbase + 16384u;

    int tid = threadIdx.x;
    cudaGridDependencySynchronize();   // needs g_rec (k2), g_wt/g_xh (k1)

    if (tid < 32) {
        int nt = (G.hist[tid] + 127) >> 7;
        int a = nt;
        #pragma unroll
        for (int o = 1; o < 32; o <<= 1) {
            int v = __shfl_up_sync(0xFFFFFFFFu, a, o);
            if (tid >= o) a += v;
        }
        Tst[tid] = a - nt;
        if (tid == 31) Tst[32] = a;
    }
    __syncthreads();
    int ntiles = Tst[32];
    int work = blockIdx.x;
    if (work >= 2 * ntiles) return;

    int dir = work >= ntiles;
    int tile = work - dir * ntiles;
    int r = 0;
    while (r < 31 && Tst[r + 1] <= tile) r++;

    int m = tid & 127;
    int4 rec = g_rec[tile * 128 + m];
    int s    = dir ? rec.y : rec.x;
    int dsti = dir ? rec.x : rec.y;
    float c  = __int_as_float(dir ? rec.w : rec.z);
    if (tid < 128) { Ds[tid] = dsti; Cs[tid] = c; }

    {   // B tile: fp16 pre-swizzled in g_wt — straight cp.async (8KB)
        const __half* wt = g_wt + (size_t)((dir << 5) + r) * 4096;
        cpa16(sB + (unsigned)tid * 16u, wt + tid * 8);
        cpa16(sB + (unsigned)(tid + 256) * 16u, wt + (tid + 256) * 8);
    }
    {   // A rows from g_xh via cp.async (16KB)
        int h = tid >> 7;
        const __half* xr = g_xh + (size_t)s * C;
        #pragma unroll
        for (int q = 0; q < 4; q++) {
            int g = h * 4 + q;
            cpa16(sA + (unsigned)(m * 128 + ((g ^ (m & 7)) << 4)), xr + g * 8);
        }
    }
    asm volatile("cp.async.commit_group;" ::: "memory");
    asm volatile("cp.async.wait_group 0;" ::: "memory");
    __syncthreads();

    int lane = tid & 31, w = tid >> 5;
    float d[8][4] = {};
    mma_main(sA, sB, lane, w, d);

    // epilogue (no extra sync needed: Ds/Cs never overwritten)
    int gid = lane >> 2, tig = lane & 3;
    int r0 = w * 16 + gid, r1 = r0 + 8;
    int d0i = Ds[r0], d1i = Ds[r1];
    float c0 = Cs[r0], c1 = Cs[r1];
    bool v0 = (c0 != 0.f), v1 = (c1 != 0.f);
    bool lowlane = !(tig & 1);
    #pragma unroll
    for (int j = 0; j < 8; j++) {
        float a0 = d[j][0] * c0, a1 = d[j][1] * c0;
        float b0 = d[j][2] * c1, b1 = d[j][3] * c1;
        float a2 = __shfl_xor_sync(0xFFFFFFFFu, a0, 1);
        float a3 = __shfl_xor_sync(0xFFFFFFFFu, a1, 1);
        float b2 = __shfl_xor_sync(0xFFFFFFFFu, b0, 1);
        float b3 = __shfl_xor_sync(0xFFFFFFFFu, b1, 1);
        if (lowlane) {
            int n = j * 8 + 2 * tig;
            if (v0) red4(out + (size_t)d0i * C + n, a0, a1, a2, a3);
            if (v1) red4(out + (size_t)d1i * C + n, b0, b1, b2, b3);
        }
    }
}

// ---------------- launch (PDL-chained) ----------------
extern "C" void kernel_launch(void* const* d_in, const int* in_sizes, int n_in,
                              void* d_out, int out_size)
{
    const float* x  = (const float*)d_in[0];
    const void*  ei = d_in[1];
    const void*  et = d_in[2];
    const float* wf = (const float*)d_in[3];
    const float* wb = (const float*)d_in[4];
    const float* lw = (const float*)d_in[5];
    const float* lb = (const float*)d_in[6];
    float* out = (float*)d_out;

    cudaFuncSetAttribute(k_conv, cudaFuncAttributeMaxDynamicSharedMemorySize,
                         CONV_SMEM_BYTES);
    cudaFuncSetAttribute(k_scatlin, cudaFuncAttributeMaxDynamicSharedMemorySize,
                         SCAT_SMEM_BYTES);

    cudaLaunchAttribute pdl[1];
    pdl[0].id = cudaLaunchAttributeProgrammaticStreamSerialization;
    pdl[0].val.programmaticStreamSerializationAllowed = 1;

    k_zero<<<ZERO_BLOCKS + 1, 256>>>(ei);
    {
        cudaLaunchConfig_t cfg = {};
        cfg.gridDim = dim3(XH_BLOCKS + 64 + COUNT_BLOCKS);
        cfg.blockDim = dim3(256);
        cfg.attrs = pdl; cfg.numAttrs = 1;
        cudaLaunchKernelEx(&cfg, k_cnx, ei, et, wf, wb, x);
    }
    {
        cudaLaunchConfig_t cfg = {};
        cfg.gridDim = dim3(LIN_BLOCKS + 1 + SCAT_BLOCKS);
        cfg.blockDim = dim3(256);
        cfg.dynamicSmemBytes = SCAT_SMEM_BYTES;
        cfg.attrs = pdl; cfg.numAttrs = 1;
        cudaLaunchKernelEx(&cfg, k_scatlin, ei, et, x, lw, lb, out);
    }
    {
        cudaLaunchConfig_t cfg = {};
        cfg.gridDim = dim3(CONV_GRID);
        cfg.blockDim = dim3(256);
        cfg.dynamicSmemBytes = CONV_SMEM_BYTES;
        cfg.attrs = pdl; cfg.numAttrs = 1;
        cudaLaunchKernelEx(&cfg, k_conv, out);
    }
}

// round 15
// speedup vs baseline: 1.0651x; 1.0651x over previous
#include <cuda_runtime.h>
#include <cuda_fp16.h>
#include <math.h>

#define N_NODES 20000
#define N_EDGES 50000
#define C 64
#define NREL 32
#define MAXTILES 424
#define ORDER_CAP (MAXTILES * 128)   // 54272

// ---------------- scratch (no allocations allowed) ----------------
struct __align__(16) GScratch {
    int cnt_src[N_NODES];
    int cnt_dst[N_NODES];
    int hist[NREL];
    int cursor[NREL];
};
__device__ GScratch G;
__device__ __align__(16) int4   g_rec[ORDER_CAP];       // src,dst,c0,c1 (pads: c=0)
__device__ __align__(16) __half g_wt[2 * NREL * 4096];  // fp16, n-major, swizzled
__device__ __align__(16) __half g_xh[N_NODES * C];      // fp16 copy of x
__device__ float g_inv[2][NREL];
__device__ int g_is64;

__device__ __forceinline__ int load_idx(const void* p, int i, int is64) {
    return is64 ? (int)((const long long*)p)[i] : ((const int*)p)[i];
}
__device__ __forceinline__ void mma_f16(float* d,
    unsigned a0, unsigned a1, unsigned a2, unsigned a3,
    unsigned b0, unsigned b1)
{
    asm volatile(
        "mma.sync.aligned.m16n8k16.row.col.f32.f16.f16.f32 "
        "{%0,%1,%2,%3},{%4,%5,%6,%7},{%8,%9},{%0,%1,%2,%3};"
        : "+f"(d[0]), "+f"(d[1]), "+f"(d[2]), "+f"(d[3])
        : "r"(a0), "r"(a1), "r"(a2), "r"(a3), "r"(b0), "r"(b1));
}
__device__ __forceinline__ void ldsm4(unsigned& r0, unsigned& r1,
                                      unsigned& r2, unsigned& r3, unsigned addr)
{
    asm volatile("ldmatrix.sync.aligned.m8n8.x4.shared.b16 {%0,%1,%2,%3}, [%4];"
                 : "=r"(r0), "=r"(r1), "=r"(r2), "=r"(r3) : "r"(addr));
}
__device__ __forceinline__ void red4(float* p, float a, float b, float c, float d) {
    asm volatile("red.global.add.v4.f32 [%0], {%1,%2,%3,%4};"
                 :: "l"(p), "f"(a), "f"(b), "f"(c), "f"(d) : "memory");
}
__device__ __forceinline__ void cpa16(unsigned dst, const void* src) {
    asm volatile("cp.async.ca.shared.global [%0], [%1], 16;"
                 :: "r"(dst), "l"(src) : "memory");
}
// fp16 tile layout: rows of 64 halves (128B), 8x16B groups, group XOR by row&7
__device__ __forceinline__ int swzh(int row, int k) {
    return row * 64 + (((k >> 3) ^ (row & 7)) << 3) + (k & 7);
}

#define N16_G ((int)(sizeof(GScratch) / 16))
#define ZERO_BLOCKS ((N16_G + 255) / 256)         // 40
#define XH_BLOCKS ((N_NODES * C) / 2048)          // 625
#define COUNT_BLOCKS ((N_EDGES + 255) / 256)      // 196

// ---------------- k0: zero counters + detect index width --------------------
__global__ __launch_bounds__(256) void k_zero(const void* __restrict__ ei)
{
    int b = blockIdx.x, tid = threadIdx.x;
    if (b < ZERO_BLOCKS) {
        int i = b * 256 + tid;
        if (i < N16_G) ((int4*)&G)[i] = make_int4(0, 0, 0, 0);
    } else {
        if (tid < 32) {
            int hi = ((const int*)ei)[2 * tid + 1];
            unsigned ok = __ballot_sync(0xFFFFFFFFu, hi == 0);
            if (tid == 0) g_is64 = (ok == 0xFFFFFFFFu) ? 1 : 0;
        }
    }
}

// ---------------- k1: count (PDL-dep) || norms+W || x->fp16 -----------------
__global__ __launch_bounds__(256) void k_cnx(
    const void* __restrict__ ei, const void* __restrict__ et,
    const float* __restrict__ wf, const float* __restrict__ wb,
    const float* __restrict__ x)
{
    int b = blockIdx.x, tid = threadIdx.x;
    if (b < COUNT_BLOCKS) {
        __shared__ int h[NREL];
        if (tid < NREL) h[tid] = 0;
        cudaGridDependencySynchronize();   // needs zeroed G + g_is64
        __syncthreads();
        int e = b * 256 + tid;
        int is64 = g_is64;
        if (e < N_EDGES) {
            atomicAdd(&G.cnt_src[load_idx(ei, e, is64)], 1);
            atomicAdd(&G.cnt_dst[load_idx(ei, N_EDGES + e, is64)], 1);
            atomicAdd(&h[load_idx(et, e, is64)], 1);
        }
        __syncthreads();
        if (tid < NREL && h[tid]) atomicAdd(&G.hist[tid], h[tid]);
    } else if (b < COUNT_BLOCKS + 64) {
        __shared__ float red[256];
        int bb = b - COUNT_BLOCKS;
        int r = bb & 31, tab = bb >> 5;
        const float* w = (tab ? wb : wf) + (size_t)r * (C * C);
        __half* wt = g_wt + (size_t)bb * 4096;
        float s = 0.f;
        for (int j = tid; j < C * C; j += 256) {
            float v = w[j];
            s += v * v;
            int k = j >> 6, n = j & 63;          // gmem is [k][n]
            wt[swzh(n, k)] = __float2half_rn(v);
        }
        red[tid] = s; __syncthreads();
        for (int o = 128; o > 0; o >>= 1) {
            if (tid < o) red[tid] += red[tid + o];
            __syncthreads();
        }
        if (tid == 0) g_inv[tab][r] = 1.f / (sqrtf(red[0]) + 0.01f);
    } else {
        int i = (b - COUNT_BLOCKS - 64) * 2048 + tid * 8;
        float4 v0 = *(const float4*)(x + i);
        float4 v1 = *(const float4*)(x + i + 4);
        __half h[8];
        h[0]=__float2half_rn(v0.x); h[1]=__float2half_rn(v0.y);
        h[2]=__float2half_rn(v0.z); h[3]=__float2half_rn(v0.w);
        h[4]=__float2half_rn(v1.x); h[5]=__float2half_rn(v1.y);
        h[6]=__float2half_rn(v1.z); h[7]=__float2half_rn(v1.w);
        *(int4*)(g_xh + i) = *(int4*)h;
    }
}

// ====== fp16 tensor-core inner loop: 128x64 @ k=64, m16n8k16 ================
__device__ __forceinline__ void mma_main(
    unsigned sA, unsigned sB, int lane, int warp, float d[8][4])
{
    int arow = warp * 16 + (lane & 15);
    unsigned arowoff = (unsigned)arow * 128u;
    int ax = arow & 7;
    int aksel = lane >> 4;
    int nb = (lane & 7) + ((lane & 16) >> 1);
    int bksel = (lane >> 3) & 1;

    #pragma unroll
    for (int t = 0; t < 4; t++) {
        unsigned apg = (unsigned)((2 * t + aksel) ^ ax);
        unsigned a0, a1, a2, a3;
        ldsm4(a0, a1, a2, a3, sA + arowoff + apg * 16u);
        #pragma unroll
        for (int j = 0; j < 4; j++) {
            int n = 16 * j + nb;
            unsigned bpg = (unsigned)((2 * t + bksel) ^ (n & 7));
            unsigned b0, b1, b2, b3;
            ldsm4(b0, b1, b2, b3, sB + (unsigned)n * 128u + bpg * 16u);
            mma_f16(d[2 * j],     a0, a1, a2, a3, b0, b1);
            mma_f16(d[2 * j + 1], a0, a1, a2, a3, b2, b3);
        }
    }
}

// ---------------- k2: scatter + pad-fill + linear term ----------------------
#define SCAT_BLOCKS COUNT_BLOCKS
#define LIN_BLOCKS ((N_NODES + 127) / 128)
#define TC_SMEM_BYTES (16384 + 8192)             // A 16KB + B 8KB
#define SCAT_SMEM_BYTES TC_SMEM_BYTES

__global__ __launch_bounds__(256, 4) void k_scatlin(
    const void* __restrict__ ei, const void* __restrict__ et,
    const float* __restrict__ lw, const float* __restrict__ lb,
    float* __restrict__ out)
{
    int tid = threadIdx.x;
    cudaGridDependencySynchronize();   // needs hist/cnt/inv + g_xh (k1)

    if (blockIdx.x < SCAT_BLOCKS) {
        __shared__ int obase[NREL];
        __shared__ int bcnt[NREL];
        __shared__ int gbase[NREL];
        if (tid < 32) {
            int nt = (G.hist[tid] + 127) >> 7;
            int a = nt;
            #pragma unroll
            for (int o = 1; o < 32; o <<= 1) {
                int v = __shfl_up_sync(0xFFFFFFFFu, a, o);
                if (tid >= o) a += v;
            }
            obase[tid] = (a - nt) * 128;
            bcnt[tid] = 0;
        }
        __syncthreads();
        int is64 = g_is64;
        int e = blockIdx.x * 256 + tid;
        int r = 0, my = 0, valid = (e < N_EDGES);
        if (valid) {
            r = load_idx(et, e, is64);
            my = atomicAdd(&bcnt[r], 1);
        }
        __syncthreads();
        if (tid < 32 && bcnt[tid]) gbase[tid] = atomicAdd(&G.cursor[tid], bcnt[tid]);
        __syncthreads();
        if (valid) {
            int pos = obase[r] + gbase[r] + my;
            int s  = load_idx(ei, e, is64);
            int dd = load_idx(ei, N_EDGES + e, is64);
            float c0 = g_inv[0][r] / (float)(G.cnt_src[s] + 1);
            float c1 = g_inv[1][r] / (float)(G.cnt_dst[dd] + 1);
            g_rec[pos] = make_int4(s, dd, __float_as_int(c0), __float_as_int(c1));
        }
        return;
    }
    if (blockIdx.x == SCAT_BLOCKS) {
        // pad-fill zero records per relation
        __shared__ int pbase[NREL];
        __shared__ int pcnt[NREL];
        if (tid < 32) {
            int h = G.hist[tid];
            int nt = (h + 127) >> 7;
            int a = nt;
            #pragma unroll
            for (int o = 1; o < 32; o <<= 1) {
                int v = __shfl_up_sync(0xFFFFFFFFu, a, o);
                if (tid >= o) a += v;
            }
            pbase[tid] = (a - nt) * 128 + h;
            pcnt[tid]  = nt * 128 - h;
        }
        __syncthreads();
        for (int r = 0; r < NREL; r++) {
            int pn = pcnt[r];
            for (int i = tid; i < pn; i += 256)
                g_rec[pbase[r] + i] = make_int4(0, 0, 0, 0);
        }
        return;
    }

    // ---- linear: out = x @ lw^T + b (fp16 mma), coalesced A-load ----
    extern __shared__ char smc[];
    __half* Bh = (__half*)(smc + 16384);
    unsigned sbase = (unsigned)__cvta_generic_to_shared(smc);
    unsigned sA = sbase, sB = sbase + 16384u;

    int node0 = (blockIdx.x - SCAT_BLOCKS - 1) * 128;

    {   // A: 8 lanes cover one row's 128B (fully-coalesced cp.async)
        int g = tid & 7, rb = tid >> 3;
        #pragma unroll
        for (int p = 0; p < 4; p++) {
            int row = rb + p * 32;
            int node = node0 + row;
            if (node >= N_NODES) node = 0;
            cpa16(sA + (unsigned)(row * 128 + ((g ^ (row & 7)) << 4)),
                  g_xh + (size_t)node * C + g * 8);
        }
        asm volatile("cp.async.commit_group;" ::: "memory");
    }
    {   // B = lw -> fp16 swizzled
        const float4* w4 = (const float4*)lw;
        #pragma unroll
        for (int q = 0; q < 4; q++) {
            int i4 = tid + 256 * q;
            float4 v = w4[i4];
            int n = i4 >> 4, k0 = (i4 & 15) * 4;
            __half hh[4];
            hh[0]=__float2half_rn(v.x); hh[1]=__float2half_rn(v.y);
            hh[2]=__float2half_rn(v.z); hh[3]=__float2half_rn(v.w);
            *(uint2*)&Bh[swzh(n, k0)] = *(uint2*)hh;
        }
    }
    asm volatile("cp.async.wait_group 0;" ::: "memory");
    __syncthreads();

    int lane = tid & 31, w = tid >> 5;
    float d[8][4] = {};
    mma_main(sA, sB, lane, w, d);

    int gid = lane >> 2, tig = lane & 3;
    int r0 = w * 16 + gid, r1 = r0 + 8;
    #pragma unroll
    for (int j = 0; j < 8; j++) {
        int n = j * 8 + 2 * tig;
        float2 bias = *(const float2*)(lb + n);
        if (node0 + r0 < N_NODES)
            *(float2*)(out + (size_t)(node0 + r0) * C + n) =
                make_float2(d[j][0] + bias.x, d[j][1] + bias.y);
        if (node0 + r1 < N_NODES)
            *(float2*)(out + (size_t)(node0 + r1) * C + n) =
                make_float2(d[j][2] + bias.x, d[j][3] + bias.y);
    }
}

// ---------------- k3: conv (one-shot; coalesced gather; guarded red4) -------
#define CONV_SMEM_BYTES (TC_SMEM_BYTES + (128 * 3 + 33) * 4)
#define CONV_GRID (2 * (MAXTILES - 2))            // 844

__global__ __launch_bounds__(256, 4) void k_conv(float* __restrict__ out)
{
    extern __shared__ char smc[];
    int*   Ds  = (int*)(smc + 24576);
    float* Cs  = (float*)(Ds + 128);
    int*   Ss  = (int*)(Cs + 128);
    int*   Tst = (int*)(Ss + 128);
    unsigned sbase = (unsigned)__cvta_generic_to_shared(smc);
    unsigned sA = sbase, sB = sbase + 16384u;

    int tid = threadIdx.x;
    cudaGridDependencySynchronize();   // needs g_rec (k2), g_wt/g_xh (k1)

    if (tid < 32) {
        int nt = (G.hist[tid] + 127) >> 7;
        int a = nt;
        #pragma unroll
        for (int o = 1; o < 32; o <<= 1) {
            int v = __shfl_up_sync(0xFFFFFFFFu, a, o);
            if (tid >= o) a += v;
        }
        Tst[tid] = a - nt;
        if (tid == 31) Tst[32] = a;
    }
    __syncthreads();
    int ntiles = Tst[32];
    int work = blockIdx.x;
    if (work >= 2 * ntiles) return;

    int dir = work >= ntiles;
    int tile = work - dir * ntiles;
    int r = 0;
    while (r < 31 && Tst[r + 1] <= tile) r++;

    // only 128 threads load recs; stash src/dst/coef in smem
    if (tid < 128) {
        int4 rec = g_rec[tile * 128 + tid];
        Ss[tid] = dir ? rec.y : rec.x;
        Ds[tid] = dir ? rec.x : rec.y;
        Cs[tid] = __int_as_float(dir ? rec.w : rec.z);
    }
    {   // B tile: fp16 pre-swizzled in g_wt — straight cp.async (8KB)
        const __half* wt = g_wt + (size_t)((dir << 5) + r) * 4096;
        cpa16(sB + (unsigned)tid * 16u, wt + tid * 8);
        cpa16(sB + (unsigned)(tid + 256) * 16u, wt + (tid + 256) * 8);
    }
    __syncthreads();   // Ss visible to all before gather

    {   // A gather: 8 lanes cover one row's full 128B (coalesced sectors)
        int g = tid & 7, rb = tid >> 3;
        #pragma unroll
        for (int p = 0; p < 4; p++) {
            int row = rb + p * 32;
            cpa16(sA + (unsigned)(row * 128 + ((g ^ (row & 7)) << 4)),
                  g_xh + (size_t)Ss[row] * C + g * 8);
        }
    }
    asm volatile("cp.async.commit_group;" ::: "memory");
    asm volatile("cp.async.wait_group 0;" ::: "memory");
    __syncthreads();

    int lane = tid & 31, w = tid >> 5;
    float d[8][4] = {};
    mma_main(sA, sB, lane, w, d);

    // epilogue: scale, pair-combine via shfl, red.v4 — guarded (c==0 = pad)
    int gid = lane >> 2, tig = lane & 3;
    int r0 = w * 16 + gid, r1 = r0 + 8;
    int d0i = Ds[r0], d1i = Ds[r1];
    float c0 = Cs[r0], c1 = Cs[r1];
    bool v0 = (c0 != 0.f), v1 = (c1 != 0.f);
    bool lowlane = !(tig & 1);
    #pragma unroll
    for (int j = 0; j < 8; j++) {
        float a0 = d[j][0] * c0, a1 = d[j][1] * c0;
        float b0 = d[j][2] * c1, b1 = d[j][3] * c1;
        float a2 = __shfl_xor_sync(0xFFFFFFFFu, a0, 1);
        float a3 = __shfl_xor_sync(0xFFFFFFFFu, a1, 1);
        float b2 = __shfl_xor_sync(0xFFFFFFFFu, b0, 1);
        float b3 = __shfl_xor_sync(0xFFFFFFFFu, b1, 1);
        if (lowlane) {
            int n = j * 8 + 2 * tig;
            if (v0) red4(out + (size_t)d0i * C + n, a0, a1, a2, a3);
            if (v1) red4(out + (size_t)d1i * C + n, b0, b1, b2, b3);
        }
    }
}

// ---------------- launch (PDL-chained, R13 ordering) ----------------
extern "C" void kernel_launch(void* const* d_in, const int* in_sizes, int n_in,
                              void* d_out, int out_size)
{
    const float* x  = (const float*)d_in[0];
    const void*  ei = d_in[1];
    const void*  et = d_in[2];
    const float* wf = (const float*)d_in[3];
    const float* wb = (const float*)d_in[4];
    const float* lw = (const float*)d_in[5];
    const float* lb = (const float*)d_in[6];
    float* out = (float*)d_out;

    cudaFuncSetAttribute(k_conv, cudaFuncAttributeMaxDynamicSharedMemorySize,
                         CONV_SMEM_BYTES);
    cudaFuncSetAttribute(k_scatlin, cudaFuncAttributeMaxDynamicSharedMemorySize,
                         SCAT_SMEM_BYTES);

    cudaLaunchAttribute pdl[1];
    pdl[0].id = cudaLaunchAttributeProgrammaticStreamSerialization;
    pdl[0].val.programmaticStreamSerializationAllowed = 1;

    k_zero<<<ZERO_BLOCKS + 1, 256>>>(ei);
    {
        cudaLaunchConfig_t cfg = {};
        cfg.gridDim = dim3(COUNT_BLOCKS + 64 + XH_BLOCKS);
        cfg.blockDim = dim3(256);
        cfg.attrs = pdl; cfg.numAttrs = 1;
        cudaLaunchKernelEx(&cfg, k_cnx, ei, et, wf, wb, x);
    }
    {
        cudaLaunchConfig_t cfg = {};
        cfg.gridDim = dim3(SCAT_BLOCKS + 1 + LIN_BLOCKS);
        cfg.blockDim = dim3(256);
        cfg.dynamicSmemBytes = SCAT_SMEM_BYTES;
        cfg.attrs = pdl; cfg.numAttrs = 1;
        cudaLaunchKernelEx(&cfg, k_scatlin, ei, et, lw, lb, out);
    }
    {
        cudaLaunchConfig_t cfg = {};
        cfg.gridDim = dim3(CONV_GRID);
        cfg.blockDim = dim3(256);
        cfg.dynamicSmemBytes = CONV_SMEM_BYTES;
        cfg.attrs = pdl; cfg.numAttrs = 1;
        cudaLaunchKernelEx(&cfg, k_conv, out);
    }
}